// round 1
// baseline (speedup 1.0000x reference)
#include <cuda_runtime.h>
#include <cuda_bf16.h>
#include <cstdint>

#define N_NODES 100000
#define N_EDGES 1250000
#define D       64

// Scratch (no allocs allowed): 25.6MB agg + deg + norm
__device__ float g_agg[(size_t)N_NODES * D];
__device__ int   g_deg[N_NODES];
__device__ float g_norm[N_NODES];

// ---------------------------------------------------------------------------
// K1: zero agg + deg
__global__ void k_init() {
    int i = blockIdx.x * 256 + threadIdx.x;
    if (i < N_NODES * D) g_agg[i] = 0.0f;
    if (i < N_NODES)     g_deg[i] = 0;
}

// K2: degree count
__global__ void k_deg(const int* __restrict__ dst) {
    int e = blockIdx.x * 256 + threadIdx.x;
    if (e < N_EDGES) atomicAdd(&g_deg[dst[e]], 1);
}

// K3: norm = clip(deg,1)^-0.5
__global__ void k_norm() {
    int i = blockIdx.x * 256 + threadIdx.x;
    if (i < N_NODES) g_norm[i] = rsqrtf(fmaxf((float)g_deg[i], 1.0f));
}

// K4: edge scatter: agg[dst] += feat[src] * norm[src]
// 16 lanes per edge; each lane: float4 gather + one red.global.add.v4.f32
__global__ void k_scatter(const float* __restrict__ feat,
                          const int* __restrict__ src,
                          const int* __restrict__ dst) {
    int t = blockIdx.x * 256 + threadIdx.x;
    int e = t >> 4;
    int sub = t & 15;
    if (e >= N_EDGES) return;
    int s = __ldg(&src[e]);
    int d = __ldg(&dst[e]);
    float ns = g_norm[s];
    float4 v = *reinterpret_cast<const float4*>(feat + (size_t)s * D + sub * 4);
    v.x *= ns; v.y *= ns; v.z *= ns; v.w *= ns;
    float* p = g_agg + (size_t)d * D + sub * 4;
    asm volatile("red.global.add.v4.f32 [%0], {%1, %2, %3, %4};"
                 :: "l"(p), "f"(v.x), "f"(v.y), "f"(v.z), "f"(v.w)
                 : "memory");
}

// K5: out = (agg * norm[dstnode]) @ W^T + bias
// 4 nodes per 256-thread block; W in smem padded to 65 floats/row (no bank conflicts)
__global__ void k_out(const float* __restrict__ W,
                      const float* __restrict__ bias,
                      float* __restrict__ out) {
    __shared__ float w_sm[64 * 65];
    __shared__ float a_sm[4 * 64];
    int tid = threadIdx.x;

    for (int idx = tid; idx < 64 * 64; idx += 256) {
        int r = idx >> 6, c = idx & 63;
        w_sm[r * 65 + c] = W[idx];
    }
    int node0 = blockIdx.x * 4;
    {
        int ln = tid >> 6, k = tid & 63;
        int n = node0 + ln;
        a_sm[tid] = g_agg[(size_t)n * D + k] * g_norm[n];
    }
    __syncthreads();

    int ln = tid >> 6, j = tid & 63;
    float acc = bias[j];
    const float* a = &a_sm[ln * 64];
    const float* w = &w_sm[j * 65];
#pragma unroll
    for (int k = 0; k < 64; k++) acc = fmaf(a[k], w[k], acc);
    out[(size_t)(node0 + ln) * D + j] = acc;
}

// ---------------------------------------------------------------------------
extern "C" void kernel_launch(void* const* d_in, const int* in_sizes, int n_in,
                              void* d_out, int out_size) {
    const float* feat = (const float*)d_in[0];
    const int*   src  = (const int*)d_in[1];
    const int*   dst  = (const int*)d_in[2];
    const float* W    = (const float*)d_in[3];
    const float* bias = (const float*)d_in[4];
    float* out = (float*)d_out;

    k_init<<<(N_NODES * D + 255) / 256, 256>>>();
    k_deg<<<(N_EDGES + 255) / 256, 256>>>(dst);
    k_norm<<<(N_NODES + 255) / 256, 256>>>();
    k_scatter<<<(N_EDGES * 16 + 255) / 256, 256>>>(feat, src, dst);
    k_out<<<N_NODES / 4, 256>>>(W, bias, out);
}

// round 2
// speedup vs baseline: 1.6693x; 1.6693x over previous
#include <cuda_runtime.h>
#include <cuda_bf16.h>
#include <cstdint>

#define N_NODES 100000
#define N_EDGES 1250000
#define D       64

// Scratch (no allocs allowed)
__device__ float g_agg[(size_t)N_NODES * D];
__device__ int   g_deg[N_NODES];
__device__ float g_norm[N_NODES];

// ---------------------------------------------------------------------------
// K1: zero agg (vectorized) + deg
__global__ void k_init() {
    int i = blockIdx.x * 256 + threadIdx.x;
    if (i < N_NODES * D / 4) reinterpret_cast<float4*>(g_agg)[i] = make_float4(0.f, 0.f, 0.f, 0.f);
    if (i < N_NODES)         g_deg[i] = 0;
}

// K2: degree count (red, no return)
__global__ void k_deg(const int* __restrict__ dst) {
    int e = blockIdx.x * 256 + threadIdx.x;
    if (e < N_EDGES) atomicAdd(&g_deg[dst[e]], 1);
}

// K3: norm = clip(deg,1)^-0.5
__global__ void k_norm() {
    int i = blockIdx.x * 256 + threadIdx.x;
    if (i < N_NODES) g_norm[i] = rsqrtf(fmaxf((float)g_deg[i], 1.0f));
}

// K4: edge scatter: agg[dst] += feat[src] * norm[src]
// 16 lanes per edge-group; each thread processes 4 edges (MLP=4 gathers in flight).
#define EDGE_GROUPS (N_EDGES / 4)   // 312500, N_EDGES divisible by 4
__global__ void k_scatter(const float* __restrict__ feat,
                          const int* __restrict__ src,
                          const int* __restrict__ dst) {
    int t = blockIdx.x * 256 + threadIdx.x;
    int grp = t >> 4;
    int sub = t & 15;
    if (grp >= EDGE_GROUPS) return;
    int e0 = grp * 4;
    // all 16 lanes of a group load the same int4 (coalesced/broadcast)
    int4 s4 = *reinterpret_cast<const int4*>(src + e0);
    int4 d4 = *reinterpret_cast<const int4*>(dst + e0);
    int s[4] = {s4.x, s4.y, s4.z, s4.w};
    int d[4] = {d4.x, d4.y, d4.z, d4.w};

    float  nm[4];
    float4 v[4];
#pragma unroll
    for (int i = 0; i < 4; i++) nm[i] = __ldg(&g_norm[s[i]]);
#pragma unroll
    for (int i = 0; i < 4; i++)
        v[i] = *reinterpret_cast<const float4*>(feat + (size_t)s[i] * D + sub * 4);
#pragma unroll
    for (int i = 0; i < 4; i++) {
        float4 w = v[i];
        w.x *= nm[i]; w.y *= nm[i]; w.z *= nm[i]; w.w *= nm[i];
        float* p = g_agg + (size_t)d[i] * D + sub * 4;
        asm volatile("red.global.add.v4.f32 [%0], {%1, %2, %3, %4};"
                     :: "l"(p), "f"(w.x), "f"(w.y), "f"(w.z), "f"(w.w)
                     : "memory");
    }
}

// ---------------------------------------------------------------------------
// K5: out = (agg * norm) @ W^T + bias
// One node per thread, 64 fp32 accumulators in registers.
// W transposed in smem, read with LDS.128 broadcast (1 LDS per 4 FMA).
// a staged coalesced into smem with pad-65 rows (conflict-free reads).
#define WT_PAD 68                     // floats per w_sm row (mult of 4, 16B-aligned)
#define A_PAD  65                     // floats per a_sm row
#define SMEM_OUT_BYTES ((64 * WT_PAD + 256 * A_PAD) * 4)   // 83,968 B

__global__ void __launch_bounds__(256, 2)
k_out(const float* __restrict__ W,
      const float* __restrict__ bias,
      float* __restrict__ out) {
    extern __shared__ float sm[];
    float* w_sm = sm;                 // [64][WT_PAD]  w_sm[k][j] = W[j][k]
    float* a_sm = sm + 64 * WT_PAD;   // [256][A_PAD]

    int tid = threadIdx.x;
    // Transpose W into smem (one-time, conflicts negligible)
    for (int i = tid; i < 64 * 64; i += 256) {
        int j = i >> 6, k = i & 63;
        w_sm[k * WT_PAD + j] = W[i];
    }
    // Stage a = g_agg * norm, coalesced float4 gmem reads
    int nbase = blockIdx.x * 256;
#pragma unroll
    for (int it = 0; it < 16; it++) {
        int li = tid + it * 256;          // float4 index within tile
        int nl = li >> 4;
        int k4 = (li & 15) << 2;
        int n  = nbase + nl;
        float4 v = make_float4(0.f, 0.f, 0.f, 0.f);
        float nmv = 0.f;
        if (n < N_NODES) {
            v   = *reinterpret_cast<const float4*>(g_agg + (size_t)n * D + k4);
            nmv = g_norm[n];
        }
        float* ap = a_sm + nl * A_PAD + k4;
        ap[0] = v.x * nmv; ap[1] = v.y * nmv; ap[2] = v.z * nmv; ap[3] = v.w * nmv;
    }
    __syncthreads();

    float4 acc[16];
#pragma unroll
    for (int jb = 0; jb < 16; jb++) acc[jb] = __ldg(reinterpret_cast<const float4*>(bias) + jb);

    const float* arow = a_sm + tid * A_PAD;
#pragma unroll 4
    for (int k = 0; k < 64; k++) {
        float ak = arow[k];
        const float4* wrow = reinterpret_cast<const float4*>(w_sm + k * WT_PAD);
#pragma unroll
        for (int jb = 0; jb < 16; jb++) {
            float4 w4 = wrow[jb];
            acc[jb].x = fmaf(ak, w4.x, acc[jb].x);
            acc[jb].y = fmaf(ak, w4.y, acc[jb].y);
            acc[jb].z = fmaf(ak, w4.z, acc[jb].z);
            acc[jb].w = fmaf(ak, w4.w, acc[jb].w);
        }
    }

    int n = nbase + tid;
    if (n < N_NODES) {
        float4* o = reinterpret_cast<float4*>(out + (size_t)n * D);
#pragma unroll
        for (int jb = 0; jb < 16; jb++) o[jb] = acc[jb];
    }
}

// ---------------------------------------------------------------------------
extern "C" void kernel_launch(void* const* d_in, const int* in_sizes, int n_in,
                              void* d_out, int out_size) {
    const float* feat = (const float*)d_in[0];
    const int*   src  = (const int*)d_in[1];
    const int*   dst  = (const int*)d_in[2];
    const float* W    = (const float*)d_in[3];
    const float* bias = (const float*)d_in[4];
    float* out = (float*)d_out;

    static bool attr_set = false;
    if (!attr_set) {
        cudaFuncSetAttribute(k_out, cudaFuncAttributeMaxDynamicSharedMemorySize,
                             SMEM_OUT_BYTES);
        attr_set = true;
    }

    k_init<<<(N_NODES * D / 4 + 255) / 256, 256>>>();
    k_deg<<<(N_EDGES + 255) / 256, 256>>>(dst);
    k_norm<<<(N_NODES + 255) / 256, 256>>>();
    k_scatter<<<(EDGE_GROUPS * 16 + 255) / 256, 256>>>(feat, src, dst);
    k_out<<<(N_NODES + 255) / 256, 256, SMEM_OUT_BYTES>>>(W, bias, out);
}

// round 3
// speedup vs baseline: 1.8335x; 1.0984x over previous
#include <cuda_runtime.h>
#include <cuda_bf16.h>
#include <cstdint>

#define N_NODES 100000
#define N_EDGES 1250000
#define D       64
#define NBLK    391           // ceil(N_NODES/256)

// Scratch (no allocs allowed)
__device__ float g_agg[(size_t)N_NODES * D];   // (sum feat[s]*norm[s]) * norm[n]
__device__ int   g_deg[N_NODES];
__device__ int   g_off[N_NODES];               // CSR offsets (exclusive scan of deg)
__device__ int   g_cursor[N_NODES];
__device__ int   g_eidx[N_EDGES];              // src ids grouped by dst
__device__ float g_norm[N_NODES];
__device__ int   g_part[512];                  // scan partials

// ---------------------------------------------------------------------------
__global__ void k_zero_deg() {
    int i = blockIdx.x * 1024 + threadIdx.x;
    if (i < N_NODES) g_deg[i] = 0;
}

// degree count, 4 edges/thread
__global__ void k_deg(const int* __restrict__ dst) {
    int t = blockIdx.x * 256 + threadIdx.x;
    if (t >= N_EDGES / 4) return;
    int4 d4 = *reinterpret_cast<const int4*>(dst + t * 4);
    atomicAdd(&g_deg[d4.x], 1);
    atomicAdd(&g_deg[d4.y], 1);
    atomicAdd(&g_deg[d4.z], 1);
    atomicAdd(&g_deg[d4.w], 1);
}

// scan pass 1: per-block exclusive scan of deg; block totals; fused norm calc
__global__ void k_scan1() {
    __shared__ int s[256];
    int tid = threadIdx.x;
    int i = blockIdx.x * 256 + tid;
    int d = (i < N_NODES) ? g_deg[i] : 0;
    if (i < N_NODES) g_norm[i] = rsqrtf(fmaxf((float)d, 1.0f));
    s[tid] = d;
    __syncthreads();
#pragma unroll
    for (int off = 1; off < 256; off <<= 1) {
        int v = (tid >= off) ? s[tid - off] : 0;
        __syncthreads();
        s[tid] += v;
        __syncthreads();
    }
    if (i < N_NODES) g_off[i] = s[tid] - d;      // local exclusive
    if (tid == 255) g_part[blockIdx.x] = s[255];
}

// scan pass 2: single block, exclusive scan of NBLK partials
__global__ void k_scan2() {
    __shared__ int s[512];
    int tid = threadIdx.x;
    int v = (tid < NBLK) ? g_part[tid] : 0;
    s[tid] = v;
    __syncthreads();
#pragma unroll
    for (int off = 1; off < 512; off <<= 1) {
        int u = (tid >= off) ? s[tid - off] : 0;
        __syncthreads();
        s[tid] += u;
        __syncthreads();
    }
    if (tid < NBLK) g_part[tid] = s[tid] - v;    // exclusive
}

// scan pass 3: add block base; init cursors
__global__ void k_scan3() {
    int i = blockIdx.x * 256 + threadIdx.x;
    if (i < N_NODES) {
        int o = g_off[i] + g_part[blockIdx.x];
        g_off[i] = o;
        g_cursor[i] = o;
    }
}

// fill CSR: group src ids by dst
__global__ void k_fill(const int* __restrict__ src, const int* __restrict__ dst) {
    int t = blockIdx.x * 256 + threadIdx.x;
    if (t >= N_EDGES / 4) return;
    int4 s4 = *reinterpret_cast<const int4*>(src + t * 4);
    int4 d4 = *reinterpret_cast<const int4*>(dst + t * 4);
    int p0 = atomicAdd(&g_cursor[d4.x], 1); g_eidx[p0] = s4.x;
    int p1 = atomicAdd(&g_cursor[d4.y], 1); g_eidx[p1] = s4.y;
    int p2 = atomicAdd(&g_cursor[d4.z], 1); g_eidx[p2] = s4.z;
    int p3 = atomicAdd(&g_cursor[d4.w], 1); g_eidx[p3] = s4.w;
}

// gather-aggregate: 16 lanes per node, register accumulation, single write.
__global__ void k_gather(const float* __restrict__ feat) {
    int t = blockIdx.x * 256 + threadIdx.x;
    int n = t >> 4;
    int sub = t & 15;
    if (n >= N_NODES) return;
    int off = g_off[n];
    int deg = g_deg[n];
    float4 acc = make_float4(0.f, 0.f, 0.f, 0.f);
    int j = 0;
    for (; j + 4 <= deg; j += 4) {
        // 4 independent index loads (broadcast across the 16 lanes)
        int s0 = __ldg(&g_eidx[off + j]);
        int s1 = __ldg(&g_eidx[off + j + 1]);
        int s2 = __ldg(&g_eidx[off + j + 2]);
        int s3 = __ldg(&g_eidx[off + j + 3]);
        float n0 = __ldg(&g_norm[s0]);
        float n1 = __ldg(&g_norm[s1]);
        float n2 = __ldg(&g_norm[s2]);
        float n3 = __ldg(&g_norm[s3]);
        float4 f0 = *reinterpret_cast<const float4*>(feat + (size_t)s0 * D + sub * 4);
        float4 f1 = *reinterpret_cast<const float4*>(feat + (size_t)s1 * D + sub * 4);
        float4 f2 = *reinterpret_cast<const float4*>(feat + (size_t)s2 * D + sub * 4);
        float4 f3 = *reinterpret_cast<const float4*>(feat + (size_t)s3 * D + sub * 4);
        acc.x += f0.x * n0 + f1.x * n1 + f2.x * n2 + f3.x * n3;
        acc.y += f0.y * n0 + f1.y * n1 + f2.y * n2 + f3.y * n3;
        acc.z += f0.z * n0 + f1.z * n1 + f2.z * n2 + f3.z * n3;
        acc.w += f0.w * n0 + f1.w * n1 + f2.w * n2 + f3.w * n3;
    }
    for (; j < deg; j++) {
        int s0 = __ldg(&g_eidx[off + j]);
        float n0 = __ldg(&g_norm[s0]);
        float4 f0 = *reinterpret_cast<const float4*>(feat + (size_t)s0 * D + sub * 4);
        acc.x += f0.x * n0; acc.y += f0.y * n0; acc.z += f0.z * n0; acc.w += f0.w * n0;
    }
    float nd = g_norm[n];
    acc.x *= nd; acc.y *= nd; acc.z *= nd; acc.w *= nd;
    *reinterpret_cast<float4*>(g_agg + (size_t)n * D + sub * 4) = acc;
}

// ---------------------------------------------------------------------------
// out = g_agg @ W^T + bias, packed f32x2 FMA (2x FFMA throughput)
#define WT_PAD 68
#define A_PAD  65
#define SMEM_OUT_BYTES ((64 * WT_PAD + 256 * A_PAD) * 4)   // 83,968 B

__global__ void __launch_bounds__(256, 2)
k_out(const float* __restrict__ W,
      const float* __restrict__ bias,
      float* __restrict__ out) {
    extern __shared__ float sm[];
    float* w_sm = sm;                 // [64][WT_PAD]  w_sm[k][j] = W[j][k]
    float* a_sm = sm + 64 * WT_PAD;   // [256][A_PAD]
    int tid = threadIdx.x;

    for (int i = tid; i < 64 * 64; i += 256) {
        int j = i >> 6, k = i & 63;
        w_sm[k * WT_PAD + j] = W[i];
    }
    int nbase = blockIdx.x * 256;
#pragma unroll
    for (int it = 0; it < 16; it++) {
        int li = tid + it * 256;
        int nl = li >> 4, k4 = (li & 15) << 2;
        int n = nbase + nl;
        float4 v = make_float4(0.f, 0.f, 0.f, 0.f);
        if (n < N_NODES) v = *reinterpret_cast<const float4*>(g_agg + (size_t)n * D + k4);
        float* ap = a_sm + nl * A_PAD + k4;
        ap[0] = v.x; ap[1] = v.y; ap[2] = v.z; ap[3] = v.w;
    }
    __syncthreads();

    unsigned long long acc[32];
#pragma unroll
    for (int i = 0; i < 32; i++)
        acc[i] = __ldg(reinterpret_cast<const unsigned long long*>(bias) + i);

    const float* arow = a_sm + tid * A_PAD;
#pragma unroll 4
    for (int k = 0; k < 64; k++) {
        float ak = arow[k];
        unsigned long long ak2;
        asm("mov.b64 %0, {%1, %1};" : "=l"(ak2) : "r"(__float_as_uint(ak)));
        const unsigned long long* wrow =
            reinterpret_cast<const unsigned long long*>(w_sm + k * WT_PAD);
#pragma unroll
        for (int i = 0; i < 32; i++)
            asm("fma.rn.f32x2 %0, %1, %2, %0;" : "+l"(acc[i]) : "l"(ak2), "l"(wrow[i]));
    }

    int n = nbase + tid;
    if (n < N_NODES) {
        ulonglong2* o = reinterpret_cast<ulonglong2*>(out + (size_t)n * D);
#pragma unroll
        for (int i = 0; i < 16; i++) o[i] = make_ulonglong2(acc[2 * i], acc[2 * i + 1]);
    }
}

// ---------------------------------------------------------------------------
extern "C" void kernel_launch(void* const* d_in, const int* in_sizes, int n_in,
                              void* d_out, int out_size) {
    const float* feat = (const float*)d_in[0];
    const int*   src  = (const int*)d_in[1];
    const int*   dst  = (const int*)d_in[2];
    const float* W    = (const float*)d_in[3];
    const float* bias = (const float*)d_in[4];
    float* out = (float*)d_out;

    static bool attr_set = false;
    if (!attr_set) {
        cudaFuncSetAttribute(k_out, cudaFuncAttributeMaxDynamicSharedMemorySize,
                             SMEM_OUT_BYTES);
        attr_set = true;
    }

    k_zero_deg<<<(N_NODES + 1023) / 1024, 1024>>>();
    k_deg<<<(N_EDGES / 4 + 255) / 256, 256>>>(dst);
    k_scan1<<<NBLK, 256>>>();
    k_scan2<<<1, 512>>>();
    k_scan3<<<NBLK, 256>>>();
    k_fill<<<(N_EDGES / 4 + 255) / 256, 256>>>(src, dst);
    k_gather<<<(N_NODES * 16 + 255) / 256, 256>>>(feat);
    k_out<<<NBLK, 256, SMEM_OUT_BYTES>>>(W, bias, out);
}